// round 1
// baseline (speedup 1.0000x reference)
#include <cuda_runtime.h>
#include <math.h>

#define NTOK   49
#define HEADS  6
#define DIM    192
#define DH     32
#define QSCALE 0.1767766952966369f   /* 32^-0.5 */

/* shared memory layout (float offsets) */
#define OFF_SX   0        /* 49*192 = 9408 floats; reused as attention-out */
#define OFF_SQ   9408     /* q  [h][n][d]           : 9408 */
#define OFF_SKT  18816    /* kT [h][d][n pad 52]    : 6*32*52 = 9984 */
#define OFF_SV   28800    /* v  [h][n][d] + 96 pad  : 9504 */
#define OFF_SWT  38304    /* weight chunk T [k][64 pad 65] : 192*65 = 12480 */
#define OFF_SP   50784    /* per-warp probs [8][7][52] : 2912 */
#define OFF_STAB 53696    /* bias table 169*6 -> pad 1016 */
#define OFF_SREL 54712    /* rel idx 2401 ints */
#define SMEM_FLOATS (54712 + 2401)
#define SMEM_BYTES  (SMEM_FLOATS * 4)   /* 228,452 B */

__global__ __launch_bounds__(256, 1)
void win_attn_fused(const float* __restrict__ x,
                    const float* __restrict__ qkv_w,
                    const float* __restrict__ qkv_b,
                    const float* __restrict__ proj_w,
                    const float* __restrict__ proj_b,
                    const float* __restrict__ bias_table,
                    const int*   __restrict__ rel_idx,
                    float* __restrict__ out)
{
    extern __shared__ float smem[];
    float* sx   = smem + OFF_SX;
    float* sq   = smem + OFF_SQ;
    float* skT  = smem + OFF_SKT;
    float* sv   = smem + OFF_SV;
    float* swT  = smem + OFF_SWT;
    float* sp   = smem + OFF_SP;
    float* stab = smem + OFF_STAB;
    int*   srel = (int*)(smem + OFF_SREL);

    const int tid = threadIdx.x;
    const int b   = blockIdx.x;

    /* ---------- phase 0: load x tile, rel idx, bias table ---------- */
    {
        const float4* xg  = (const float4*)(x + (size_t)b * (NTOK * DIM));
        float4*       sx4 = (float4*)sx;
        #pragma unroll 2
        for (int i = tid; i < NTOK * DIM / 4; i += 256) sx4[i] = xg[i];
        for (int i = tid; i < NTOK * NTOK; i += 256) srel[i] = rel_idx[i];
        for (int i = tid; i < 169 * HEADS; i += 256) stab[i] = bias_table[i];
        if (tid < 96) sv[HEADS * NTOK * DH + tid] = 0.0f;  /* v tail pad -> exact 0 */
    }
    __syncthreads();

    const int ct = tid & 63;   /* one output column per thread within a 64-col chunk */
    const int rg = tid >> 6;   /* 4 row groups; rows are rg + 4*i (rg0 gets 13 rows) */

    /* ---------- phase 1: qkv GEMM, 9 chunks of 64 cols ---------- */
    for (int cc = 0; cc < 9; cc++) {
        if (cc) __syncthreads();
        /* load weight chunk transposed: swT[k][c_local], pad 65 (conflict-free both ways) */
        for (int i = tid; i < 64 * DIM; i += 256) {
            int r = i / DIM, kk = i - r * DIM;
            swT[kk * 65 + r] = qkv_w[(cc * 64 + r) * DIM + kk];
        }
        __syncthreads();

        const int   c    = cc * 64 + ct;
        const float bias = qkv_b[c];
        float acc[13];
        #pragma unroll
        for (int i = 0; i < 13; i++) acc[i] = 0.f;

        #pragma unroll 2
        for (int k = 0; k < DIM; k += 2) {
            float w0 = swT[k * 65 + ct];
            float w1 = swT[(k + 1) * 65 + ct];
            #pragma unroll
            for (int i = 0; i < 13; i++) {
                if (i < 12 || rg == 0) {
                    int row = rg + 4 * i;
                    float2 xv = *(const float2*)&sx[row * DIM + k];  /* warp-broadcast */
                    acc[i] = fmaf(xv.x, w0, acc[i]);
                    acc[i] = fmaf(xv.y, w1, acc[i]);
                }
            }
        }

        const int which = c / DIM;
        const int r     = c - which * DIM;
        const int h     = r >> 5;
        const int d     = r & 31;
        #pragma unroll
        for (int i = 0; i < 13; i++) {
            if (i < 12 || rg == 0) {
                int row = rg + 4 * i;
                float v = acc[i] + bias;
                if (which == 0)      sq[(h * NTOK + row) * DH + d]  = v * QSCALE;
                else if (which == 1) skT[(h * DH + d) * 52 + row]   = v;
                else                 sv[(h * NTOK + row) * DH + d]  = v;
            }
        }
    }
    __syncthreads();

    /* ---------- phase 2: attention (42 units = 6 heads x 7 row-blocks over 8 warps) ---------- */
    const int wid  = tid >> 5;
    const int lane = tid & 31;
    float* sout = sx;                      /* reuse x tile for attention output */
    float* spw  = sp + wid * 7 * 52;       /* per-warp prob buffer */

    for (int u = wid; u < 42; u += 8) {
        const int h  = u / 7;
        const int n0 = (u - h * 7) * 7;
        const float* kh = skT + h * DH * 52;
        const float* qh = sq  + h * NTOK * DH;
        const float* vh = sv  + h * NTOK * DH;

        /* scores: lane owns m=lane and m=32+lane (lanes<17) */
        float a0[7], a1[7];
        #pragma unroll
        for (int i = 0; i < 7; i++) { a0[i] = 0.f; a1[i] = 0.f; }

        #pragma unroll 4
        for (int d = 0; d < DH; d++) {
            float k0 = kh[d * 52 + lane];
            float k1 = (lane < 17) ? kh[d * 52 + 32 + lane] : 0.f;
            #pragma unroll
            for (int i = 0; i < 7; i++) {
                float qv = qh[(n0 + i) * DH + d];   /* warp-broadcast */
                a0[i] = fmaf(qv, k0, a0[i]);
                a1[i] = fmaf(qv, k1, a1[i]);
            }
        }

        /* bias + softmax, probs -> smem (rows padded to 52, tail zeroed) */
        #pragma unroll
        for (int i = 0; i < 7; i++) {
            int n = n0 + i;
            float s0 = a0[i] + stab[srel[n * NTOK + lane] * HEADS + h];
            float s1 = -1e30f;
            if (lane < 17) s1 = a1[i] + stab[srel[n * NTOK + 32 + lane] * HEADS + h];
            float mx = fmaxf(s0, s1);
            #pragma unroll
            for (int off = 16; off > 0; off >>= 1)
                mx = fmaxf(mx, __shfl_xor_sync(0xffffffffu, mx, off));
            float e0 = __expf(s0 - mx);
            float e1 = (lane < 17) ? __expf(s1 - mx) : 0.f;
            float sm = e0 + e1;
            #pragma unroll
            for (int off = 16; off > 0; off >>= 1)
                sm += __shfl_xor_sync(0xffffffffu, sm, off);
            float inv = 1.f / sm;
            spw[i * 52 + lane] = e0 * inv;
            if (lane < 20) spw[i * 52 + 32 + lane] = (lane < 17) ? e1 * inv : 0.f;
        }
        __syncwarp();

        /* AV: lane owns d; float4 prob broadcast, padded tail contributes exact 0 */
        float o[7];
        #pragma unroll
        for (int i = 0; i < 7; i++) o[i] = 0.f;
        #pragma unroll 2
        for (int mq = 0; mq < 13; mq++) {
            int mb = mq * 4;
            float v0 = vh[(mb + 0) * DH + lane];
            float v1 = vh[(mb + 1) * DH + lane];
            float v2 = vh[(mb + 2) * DH + lane];
            float v3 = vh[(mb + 3) * DH + lane];
            #pragma unroll
            for (int i = 0; i < 7; i++) {
                float4 p = *(const float4*)&spw[i * 52 + mb];
                o[i] = fmaf(p.x, v0, o[i]);
                o[i] = fmaf(p.y, v1, o[i]);
                o[i] = fmaf(p.z, v2, o[i]);
                o[i] = fmaf(p.w, v3, o[i]);
            }
        }
        #pragma unroll
        for (int i = 0; i < 7; i++)
            sout[(n0 + i) * DIM + h * DH + lane] = o[i];
        __syncwarp();
    }

    /* ---------- phase 3: proj GEMM, 3 chunks of 64 cols, store to gmem ---------- */
    float* outg = out + (size_t)b * (NTOK * DIM);
    for (int cc = 0; cc < 3; cc++) {
        __syncthreads();
        for (int i = tid; i < 64 * DIM; i += 256) {
            int r = i / DIM, kk = i - r * DIM;
            swT[kk * 65 + r] = proj_w[(cc * 64 + r) * DIM + kk];
        }
        __syncthreads();

        const int   c    = cc * 64 + ct;
        const float bias = proj_b[c];
        float acc[13];
        #pragma unroll
        for (int i = 0; i < 13; i++) acc[i] = 0.f;

        #pragma unroll 2
        for (int k = 0; k < DIM; k += 2) {
            float w0 = swT[k * 65 + ct];
            float w1 = swT[(k + 1) * 65 + ct];
            #pragma unroll
            for (int i = 0; i < 13; i++) {
                if (i < 12 || rg == 0) {
                    int row = rg + 4 * i;
                    float2 xv = *(const float2*)&sout[row * DIM + k];
                    acc[i] = fmaf(xv.x, w0, acc[i]);
                    acc[i] = fmaf(xv.y, w1, acc[i]);
                }
            }
        }

        #pragma unroll
        for (int i = 0; i < 13; i++) {
            if (i < 12 || rg == 0) {
                int row = rg + 4 * i;
                outg[row * DIM + c] = acc[i] + bias;
            }
        }
    }
}

extern "C" void kernel_launch(void* const* d_in, const int* in_sizes, int n_in,
                              void* d_out, int out_size)
{
    const float* x          = (const float*)d_in[0];
    const float* qkv_w      = (const float*)d_in[1];
    const float* qkv_b      = (const float*)d_in[2];
    const float* proj_w     = (const float*)d_in[3];
    const float* proj_b     = (const float*)d_in[4];
    const float* bias_table = (const float*)d_in[5];
    const int*   rel_idx    = (const int*)d_in[6];
    float*       out        = (float*)d_out;

    const int nB = in_sizes[0] / (NTOK * DIM);   /* 4096 windows */

    cudaFuncSetAttribute(win_attn_fused,
                         cudaFuncAttributeMaxDynamicSharedMemorySize, SMEM_BYTES);
    win_attn_fused<<<nB, 256, SMEM_BYTES>>>(x, qkv_w, qkv_b, proj_w, proj_b,
                                            bias_table, rel_idx, out);
}